// round 9
// baseline (speedup 1.0000x reference)
#include <cuda_runtime.h>
#include <cuda_fp16.h>

// Problem constants (fixed shapes)
#define NU 100000
#define NI 50000
#define NN 150000        // NU + NI
#define D  64
#define DE 16
#define NE 1500000
#define NP 14
#define EPS 1e-5f

#define NN2 (2 * NN)     // row counters for both layers
#define NE2 (2 * NE)     // CSR slots for both layers
#define SCAN_BLK 1024
#define NB2 ((NN2 + SCAN_BLK - 1) / SCAN_BLK)  // 293
#define ROWB ((NN + 7) / 8)                     // 18750 (8 warps/block)
#define HISTB ((NE2 / 4 + 255) / 256)           // 2930

// -------- scratch (device globals; no allocation allowed) --------
__device__ __half g_yh0[NN * D];    // LN features layer 0 (fp16)
__device__ __half g_yh1[NN * D];    // LN features layer 1 (fp16)
__device__ __half g_eh [NN * DE];   // eigs fp16
__device__ float  g_x0 [NN * D];    // layer-0 output (fp32 for final avg)
__device__ int    g_cnt[NN2];       // row degrees (both layers)
__device__ int    g_rs [NN2];       // block-local scan; bumped to local END by score
__device__ int4   g_csr[NE2];       // CSR: (col, e0 bits, e1 bits, unused)
__device__ int    g_part[512];      // per-scan-block offsets (final, exclusive)
__device__ int    g_scan_ctr;

// ---------------------------------------------------------------
// K0: zero counters, reset scan counter, eigs -> fp16.
// ---------------------------------------------------------------
__global__ void prep_kernel(const float* __restrict__ eigs)
{
    int i = blockIdx.x * blockDim.x + threadIdx.x;
    if (i == 0) g_scan_ctr = 0;
    if (i < NN2) g_cnt[i] = 0;
    if (i < NN * DE / 2) {
        float2 v = ((const float2*)eigs)[i];
        ((__half2*)g_eh)[i] = __floats2half2_rn(v.x, v.y);
    }
}

// ---------------------------------------------------------------
// K1: fused LN(layer 0) + histogram(both layers).
// g_cnt pre-zeroed in K0 (no in-kernel zeroing — R3's race).
// ---------------------------------------------------------------
__global__ void ln_hist_kernel(const float* __restrict__ ue,
                               const float* __restrict__ ie,
                               const int*   __restrict__ idx)
{
    if (blockIdx.x < ROWB) {
        int row = blockIdx.x * 8 + (threadIdx.x >> 5);
        if (row >= NN) return;
        int lane = threadIdx.x & 31;

        const float* p = (row < NU) ? (ue + (size_t)row * D)
                                    : (ie + (size_t)(row - NU) * D);
        float2 v = ((const float2*)p)[lane];

        float s = v.x + v.y;
        #pragma unroll
        for (int o = 16; o; o >>= 1) s += __shfl_xor_sync(0xffffffffu, s, o);
        float mu = s * (1.0f / D);

        float dx = v.x - mu, dy = v.y - mu;
        float vs = dx * dx + dy * dy;
        #pragma unroll
        for (int o = 16; o; o >>= 1) vs += __shfl_xor_sync(0xffffffffu, vs, o);
        float inv = rsqrtf(vs * (1.0f / D) + EPS);

        ((__half2*)(g_yh0 + (size_t)row * D))[lane] =
            __floats2half2_rn(dx * inv, dy * inv);
    } else {
        int e4 = (blockIdx.x - ROWB) * blockDim.x + threadIdx.x;
        if (e4 < NE2 / 4) {
            int layer = (e4 >= NE / 4);
            const int* rows = idx + (size_t)layer * 2 * NE;
            int4 r4 = ((const int4*)rows)[e4 - layer * (NE / 4)];
            int base = layer * NN;
            atomicAdd(&g_cnt[base + r4.x], 1);
            atomicAdd(&g_cnt[base + r4.y], 1);
            atomicAdd(&g_cnt[base + r4.z], 1);
            atomicAdd(&g_cnt[base + r4.w], 1);
        }
    }
}

// ---------------------------------------------------------------
// K2: block-local exclusive scan of g_cnt -> g_rs; last finishing
// block scans the block totals -> g_part (final offsets). Consumers
// add g_part[i >> 10] at use; no scan3 pass.
// ---------------------------------------------------------------
__device__ __forceinline__ int warp_incl_scan(int x, int lane)
{
    #pragma unroll
    for (int o = 1; o < 32; o <<= 1) {
        int t = __shfl_up_sync(0xffffffffu, x, o);
        if (lane >= o) x += t;
    }
    return x;
}

__global__ void scan_kernel()
{
    __shared__ int warpsum[32];
    __shared__ int s_total;
    __shared__ int s_isLast;

    int lane = threadIdx.x & 31;
    int wid  = threadIdx.x >> 5;
    int i = blockIdx.x * SCAN_BLK + threadIdx.x;
    int v = (i < NN2) ? g_cnt[i] : 0;

    int inc = warp_incl_scan(v, lane);
    if (lane == 31) warpsum[wid] = inc;
    __syncthreads();
    if (wid == 0) {
        int s  = warpsum[lane];
        int si = warp_incl_scan(s, lane);
        warpsum[lane] = si - s;
        if (lane == 31) s_total = si;
    }
    __syncthreads();
    int excl = inc - v + warpsum[wid];
    if (i < NN2) g_rs[i] = excl;                 // block-local exclusive scan

    if (threadIdx.x == 0) {
        g_part[blockIdx.x] = s_total;
        __threadfence();
        s_isLast = (atomicAdd(&g_scan_ctr, 1) == (int)gridDim.x - 1);
    }
    __syncthreads();

    if (s_isLast) {
        int pv = (threadIdx.x < NB2) ? g_part[threadIdx.x] : 0;
        int inc2 = warp_incl_scan(pv, lane);
        __syncthreads();
        if (lane == 31) warpsum[wid] = inc2;
        __syncthreads();
        if (wid == 0) {
            int s  = warpsum[lane];
            int si = warp_incl_scan(s, lane);
            warpsum[lane] = si - s;
        }
        __syncthreads();
        int excl2 = inc2 - pv + warpsum[wid];
        if (threadIdx.x < NB2) g_part[threadIdx.x] = excl2;
    }
}

// ---------------------------------------------------------------
// K3: scores in EDGE order (4 lanes/edge) + fused CSR scatter.
// Cursor = atomicAdd on block-local g_rs, plus g_part offset at use.
// No row-sum atomics (sums computed in spmm via linearity).
// ---------------------------------------------------------------
__device__ __forceinline__ float dot8h(uint4 a, uint4 b)
{
    const __half2* ah = (const __half2*)&a;
    const __half2* bh = (const __half2*)&b;
    float d = 0.f;
    #pragma unroll
    for (int j = 0; j < 4; j++) {
        float2 af = __half22float2(ah[j]);
        float2 bf = __half22float2(bh[j]);
        d += af.x * bf.x + af.y * bf.y;
    }
    return d;
}

__global__ void score_kernel(const __half* __restrict__ yh,
                             const int*   __restrict__ rows,
                             const int*   __restrict__ cols,
                             const int*   __restrict__ pt,
                             const float* __restrict__ lam,
                             const float* __restrict__ pw,
                             int rowBase)
{
    int t = blockIdx.x * blockDim.x + threadIdx.x;
    int e = t >> 2;
    if (e >= NE) return;
    int q = t & 3;

    int r = __ldg(rows + e);
    int c = __ldg(cols + e);

    const uint4* ar = (const uint4*)(yh + (size_t)r * D);
    const uint4* bc = (const uint4*)(yh + (size_t)c * D);
    float dp = dot8h(__ldg(ar + q), __ldg(bc + q))
             + dot8h(__ldg(ar + q + 4), __ldg(bc + q + 4));

    // eigs fp16: 16 halves/node; lane q covers dims [4q, 4q+4)
    uint2 eu = __ldg((const uint2*)(g_eh + (size_t)r * DE) + q);
    uint2 ev = __ldg((const uint2*)(g_eh + (size_t)c * DE) + q);
    float2 e0f = __half22float2(*(__half2*)&eu.x);
    float2 e1f = __half22float2(*(__half2*)&eu.y);
    float2 f0f = __half22float2(*(__half2*)&ev.x);
    float2 f1f = __half22float2(*(__half2*)&ev.y);
    float ys = e0f.x * f0f.x + e0f.y * f0f.y + e1f.x * f1f.x + e1f.y * f1f.y;

    float elam = __expf(__ldg(lam));
    float p = dp * 0.125f + elam * ys;
    p += __shfl_xor_sync(0xffffffffu, p, 1);
    p += __shfl_xor_sync(0xffffffffu, p, 2);

    if (q == 0) {
        float v0 = fminf(__expf(p), 5.0f);                         // clip(exp,-5,5)
        float v1 = fminf(__expf(__ldg(pw + __ldg(pt + e))), 5.0f);
        int ridx = rowBase + r;
        int pos = atomicAdd(&g_rs[ridx], 1) + __ldg(&g_part[ridx >> 10]);
        g_csr[pos] = make_int4(c, __float_as_int(v0), __float_as_int(v1), 0);
    }
}

// ---------------------------------------------------------------
// K4: SpMM warp/row, 4-wide unroll. Accumulates both unnormalized
// branches AND the row sums in one loop (linearity), normalizes at
// the end.
//   MODE 0: epilogue LN -> yh1 fp16 + x0 fp32.
//   MODE 1: epilogue out = (emb + x0 + x)/3.
// ---------------------------------------------------------------
template<int MODE>
__global__ void spmm_kernel(const __half* __restrict__ yh,
                            int rowBase,
                            const float* __restrict__ ue,
                            const float* __restrict__ ie,
                            float* __restrict__ out)
{
    int row = blockIdx.x * 8 + (threadIdx.x >> 5);
    if (row >= NN) return;
    int lane = threadIdx.x & 31;

    int ridx = rowBase + row;
    int n  = g_cnt[ridx];
    // g_rs now holds block-local END (bumped by score); add part, sub n.
    int st = g_rs[ridx] + __ldg(&g_part[ridx >> 10]) - n;

    float s0 = 0.f, s1 = 0.f;
    float a0x = 0.f, a0y = 0.f, a1x = 0.f, a1y = 0.f;

    int i = 0;
    for (; i + 4 <= n; i += 4) {
        int4 cwA = __ldg(&g_csr[st + i]);
        int4 cwB = __ldg(&g_csr[st + i + 1]);
        int4 cwC = __ldg(&g_csr[st + i + 2]);
        int4 cwD = __ldg(&g_csr[st + i + 3]);
        __half2 hA = ((const __half2*)(yh + (size_t)cwA.x * D))[lane];
        __half2 hB = ((const __half2*)(yh + (size_t)cwB.x * D))[lane];
        __half2 hC = ((const __half2*)(yh + (size_t)cwC.x * D))[lane];
        __half2 hD = ((const __half2*)(yh + (size_t)cwD.x * D))[lane];
        float e0A = __int_as_float(cwA.y), e1A = __int_as_float(cwA.z);
        float e0B = __int_as_float(cwB.y), e1B = __int_as_float(cwB.z);
        float e0C = __int_as_float(cwC.y), e1C = __int_as_float(cwC.z);
        float e0D = __int_as_float(cwD.y), e1D = __int_as_float(cwD.z);
        float2 vA = __half22float2(hA);
        float2 vB = __half22float2(hB);
        float2 vC = __half22float2(hC);
        float2 vD = __half22float2(hD);
        a0x += e0A * vA.x + e0B * vB.x + e0C * vC.x + e0D * vD.x;
        a0y += e0A * vA.y + e0B * vB.y + e0C * vC.y + e0D * vD.y;
        a1x += e1A * vA.x + e1B * vB.x + e1C * vC.x + e1D * vD.x;
        a1y += e1A * vA.y + e1B * vB.y + e1C * vC.y + e1D * vD.y;
        s0 += (e0A + e0B) + (e0C + e0D);
        s1 += (e1A + e1B) + (e1C + e1D);
    }
    for (; i < n; i++) {
        int4 cw = __ldg(&g_csr[st + i]);
        __half2 h = ((const __half2*)(yh + (size_t)cw.x * D))[lane];
        float e0 = __int_as_float(cw.y), e1 = __int_as_float(cw.z);
        float2 v = __half22float2(h);
        a0x += e0 * v.x; a0y += e0 * v.y;
        a1x += e1 * v.x; a1y += e1 * v.y;
        s0 += e0; s1 += e1;
    }

    float i0 = 0.5f / ((s0 == 0.f) ? 1.f : s0);
    float i1 = 0.5f / ((s1 == 0.f) ? 1.f : s1);
    float ax = a0x * i0 + a1x * i1;
    float ay = a0y * i0 + a1y * i1;

    if (MODE == 0) {
        // fused LayerNorm -> yh1 (fp16), plus x0 (fp32)
        float s = ax + ay;
        #pragma unroll
        for (int o = 16; o; o >>= 1) s += __shfl_xor_sync(0xffffffffu, s, o);
        float mu = s * (1.0f / D);
        float dx = ax - mu, dy = ay - mu;
        float vs = dx * dx + dy * dy;
        #pragma unroll
        for (int o = 16; o; o >>= 1) vs += __shfl_xor_sync(0xffffffffu, vs, o);
        float inv = rsqrtf(vs * (1.0f / D) + EPS);

        ((float2*)(g_x0 + (size_t)row * D))[lane] = make_float2(ax, ay);
        ((__half2*)(g_yh1 + (size_t)row * D))[lane] =
            __floats2half2_rn(dx * inv, dy * inv);
    } else {
        const float* emb = (row < NU) ? (ue + (size_t)row * D)
                                      : (ie + (size_t)(row - NU) * D);
        float2 e = ((const float2*)emb)[lane];
        float2 x = ((const float2*)(g_x0 + (size_t)row * D))[lane];
        const float t = 1.0f / 3.0f;
        ((float2*)(out + (size_t)row * D))[lane] =
            make_float2((e.x + x.x + ax) * t, (e.y + x.y + ay) * t);
    }
}

extern "C" void kernel_launch(void* const* d_in, const int* in_sizes, int n_in,
                              void* d_out, int out_size)
{
    const float* ue   = (const float*)d_in[0];  // [NU, D]
    const float* ie   = (const float*)d_in[1];  // [NI, D]
    const float* eigs = (const float*)d_in[2];  // [NN, DE]
    const float* lam  = (const float*)d_in[3];  // [2]
    const float* pw   = (const float*)d_in[4];  // [2, NP]
    const int*   idx  = (const int*)  d_in[5];  // [2, 2, NE]
    const int*   pt   = (const int*)  d_in[6];  // [2, NE]
    float* out = (float*)d_out;

    __half* yh0 = nullptr; __half* yh1 = nullptr;
    cudaGetSymbolAddress((void**)&yh0, g_yh0);
    cudaGetSymbolAddress((void**)&yh1, g_yh1);

    int prepT = NN * DE / 2;                     // 1.2M threads (covers NN2)
    prep_kernel   <<<(prepT + 255) / 256, 256>>>(eigs);
    ln_hist_kernel<<<ROWB + HISTB, 256>>>(ue, ie, idx);
    scan_kernel   <<<NB2, SCAN_BLK>>>();

    int scoreB = (NE * 4 + 255) / 256;
    // layer 0
    score_kernel  <<<scoreB, 256>>>(yh0, idx, idx + NE, pt, lam, pw, 0);
    spmm_kernel<0><<<ROWB, 256>>>(yh0, 0, nullptr, nullptr, nullptr);
    // layer 1
    score_kernel  <<<scoreB, 256>>>(yh1, idx + 2 * NE, idx + 3 * NE,
                                    pt + NE, lam + 1, pw + NP, NN);
    spmm_kernel<1><<<ROWB, 256>>>(yh1, NN, ue, ie, out);
}

// round 10
// speedup vs baseline: 1.0222x; 1.0222x over previous
#include <cuda_runtime.h>
#include <cuda_fp16.h>

// Problem constants (fixed shapes)
#define NU 100000
#define NI 50000
#define NN 150000        // NU + NI
#define D  64
#define DE 16
#define NE 1500000
#define NP 14
#define EPS 1e-5f

#define NN2 (2 * NN)     // row counters for both layers
#define NE2 (2 * NE)     // CSR slots for both layers
#define SCAN_BLK 1024
#define NB2 ((NN2 + SCAN_BLK - 1) / SCAN_BLK)  // 293
#define ROWB ((NN + 7) / 8)                     // 18750 (8 warps/block)
#define HISTB ((NE2 / 4 + 255) / 256)           // 2930

// -------- scratch (device globals; no allocation allowed) --------
__device__ __half g_yh0[NN * D];    // LN features layer 0 (fp16)
__device__ __half g_yh1[NN * D];    // LN features layer 1 (fp16)
__device__ __half g_eh [NN * DE];   // eigs fp16
__device__ float  g_x0 [NN * D];    // layer-0 output (fp32 for final avg)
__device__ int    g_cnt[NN2];       // row degrees (both layers)
__device__ int    g_rs [NN2];       // block-local scan; bumped to local END by score
__device__ int4   g_csr[NE2];       // CSR: (col, e0 bits, e1 bits, unused)
__device__ int    g_part[512];      // per-scan-block offsets (final, exclusive)
__device__ int    g_scan_ctr;

// ---------------------------------------------------------------
// K0: zero counters, reset scan counter, eigs -> fp16.
// ---------------------------------------------------------------
__global__ void prep_kernel(const float* __restrict__ eigs)
{
    int i = blockIdx.x * blockDim.x + threadIdx.x;
    if (i == 0) g_scan_ctr = 0;
    if (i < NN2) g_cnt[i] = 0;
    if (i < NN * DE / 2) {
        float2 v = ((const float2*)eigs)[i];
        ((__half2*)g_eh)[i] = __floats2half2_rn(v.x, v.y);
    }
}

// ---------------------------------------------------------------
// K1: fused LN(layer 0) + histogram(both layers).
// g_cnt pre-zeroed in K0 (no in-kernel zeroing — R3's race).
// ---------------------------------------------------------------
__global__ void ln_hist_kernel(const float* __restrict__ ue,
                               const float* __restrict__ ie,
                               const int*   __restrict__ idx)
{
    if (blockIdx.x < ROWB) {
        int row = blockIdx.x * 8 + (threadIdx.x >> 5);
        if (row >= NN) return;
        int lane = threadIdx.x & 31;

        const float* p = (row < NU) ? (ue + (size_t)row * D)
                                    : (ie + (size_t)(row - NU) * D);
        float2 v = ((const float2*)p)[lane];

        float s = v.x + v.y;
        #pragma unroll
        for (int o = 16; o; o >>= 1) s += __shfl_xor_sync(0xffffffffu, s, o);
        float mu = s * (1.0f / D);

        float dx = v.x - mu, dy = v.y - mu;
        float vs = dx * dx + dy * dy;
        #pragma unroll
        for (int o = 16; o; o >>= 1) vs += __shfl_xor_sync(0xffffffffu, vs, o);
        float inv = rsqrtf(vs * (1.0f / D) + EPS);

        ((__half2*)(g_yh0 + (size_t)row * D))[lane] =
            __floats2half2_rn(dx * inv, dy * inv);
    } else {
        int e4 = (blockIdx.x - ROWB) * blockDim.x + threadIdx.x;
        if (e4 < NE2 / 4) {
            int layer = (e4 >= NE / 4);
            const int* rows = idx + (size_t)layer * 2 * NE;
            int4 r4 = ((const int4*)rows)[e4 - layer * (NE / 4)];
            int base = layer * NN;
            atomicAdd(&g_cnt[base + r4.x], 1);
            atomicAdd(&g_cnt[base + r4.y], 1);
            atomicAdd(&g_cnt[base + r4.z], 1);
            atomicAdd(&g_cnt[base + r4.w], 1);
        }
    }
}

// ---------------------------------------------------------------
// K2: block-local exclusive scan of g_cnt -> g_rs; last finishing
// block scans the block totals -> g_part (final offsets). Consumers
// add g_part[i >> 10] at use; no scan3 pass.
// ---------------------------------------------------------------
__device__ __forceinline__ int warp_incl_scan(int x, int lane)
{
    #pragma unroll
    for (int o = 1; o < 32; o <<= 1) {
        int t = __shfl_up_sync(0xffffffffu, x, o);
        if (lane >= o) x += t;
    }
    return x;
}

__global__ void scan_kernel()
{
    __shared__ int warpsum[32];
    __shared__ int s_total;
    __shared__ int s_isLast;

    int lane = threadIdx.x & 31;
    int wid  = threadIdx.x >> 5;
    int i = blockIdx.x * SCAN_BLK + threadIdx.x;
    int v = (i < NN2) ? g_cnt[i] : 0;

    int inc = warp_incl_scan(v, lane);
    if (lane == 31) warpsum[wid] = inc;
    __syncthreads();
    if (wid == 0) {
        int s  = warpsum[lane];
        int si = warp_incl_scan(s, lane);
        warpsum[lane] = si - s;
        if (lane == 31) s_total = si;
    }
    __syncthreads();
    int excl = inc - v + warpsum[wid];
    if (i < NN2) g_rs[i] = excl;                 // block-local exclusive scan

    if (threadIdx.x == 0) {
        g_part[blockIdx.x] = s_total;
        __threadfence();
        s_isLast = (atomicAdd(&g_scan_ctr, 1) == (int)gridDim.x - 1);
    }
    __syncthreads();

    if (s_isLast) {
        int pv = (threadIdx.x < NB2) ? g_part[threadIdx.x] : 0;
        int inc2 = warp_incl_scan(pv, lane);
        __syncthreads();
        if (lane == 31) warpsum[wid] = inc2;
        __syncthreads();
        if (wid == 0) {
            int s  = warpsum[lane];
            int si = warp_incl_scan(s, lane);
            warpsum[lane] = si - s;
        }
        __syncthreads();
        int excl2 = inc2 - pv + warpsum[wid];
        if (threadIdx.x < NB2) g_part[threadIdx.x] = excl2;
    }
}

// ---------------------------------------------------------------
// K3: scores in EDGE order, 8 lanes/edge + fused CSR scatter.
// Each lane loads ONE uint4 (16B) per feature row -> the 8 lanes
// cover the full 128B row in a single LDG wavefront (was 2 per row
// with 4 lanes/edge). Eigs: 2 dims/lane (one half2 per operand).
// No row-sum atomics (sums computed in spmm via linearity).
// ---------------------------------------------------------------
__device__ __forceinline__ float dot8h(uint4 a, uint4 b)
{
    const __half2* ah = (const __half2*)&a;
    const __half2* bh = (const __half2*)&b;
    float d = 0.f;
    #pragma unroll
    for (int j = 0; j < 4; j++) {
        float2 af = __half22float2(ah[j]);
        float2 bf = __half22float2(bh[j]);
        d += af.x * bf.x + af.y * bf.y;
    }
    return d;
}

__global__ void score_kernel(const __half* __restrict__ yh,
                             const int*   __restrict__ rows,
                             const int*   __restrict__ cols,
                             const int*   __restrict__ pt,
                             const float* __restrict__ lam,
                             const float* __restrict__ pw,
                             int rowBase)
{
    int t = blockIdx.x * blockDim.x + threadIdx.x;
    int e = t >> 3;
    if (e >= NE) return;
    int q = t & 7;

    int r = __ldg(rows + e);
    int c = __ldg(cols + e);

    // full 128B row covered by the 8 lanes: one uint4 each
    uint4 av = __ldg((const uint4*)(yh + (size_t)r * D) + q);
    uint4 bv = __ldg((const uint4*)(yh + (size_t)c * D) + q);
    float dp = dot8h(av, bv);

    // eigs fp16: 16 halves/node; lane q covers dims [2q, 2q+2)
    __half2 eu = __ldg((const __half2*)(g_eh + (size_t)r * DE) + q);
    __half2 ev = __ldg((const __half2*)(g_eh + (size_t)c * DE) + q);
    float2 ef = __half22float2(eu);
    float2 ff = __half22float2(ev);
    float ys = ef.x * ff.x + ef.y * ff.y;

    float elam = __expf(__ldg(lam));
    float p = dp * 0.125f + elam * ys;
    p += __shfl_xor_sync(0xffffffffu, p, 1);
    p += __shfl_xor_sync(0xffffffffu, p, 2);
    p += __shfl_xor_sync(0xffffffffu, p, 4);

    if (q == 0) {
        float v0 = fminf(__expf(p), 5.0f);                         // clip(exp,-5,5)
        float v1 = fminf(__expf(__ldg(pw + __ldg(pt + e))), 5.0f);
        int ridx = rowBase + r;
        int pos = atomicAdd(&g_rs[ridx], 1) + __ldg(&g_part[ridx >> 10]);
        g_csr[pos] = make_int4(c, __float_as_int(v0), __float_as_int(v1), 0);
    }
}

// ---------------------------------------------------------------
// K4: SpMM warp/row, 2-wide unroll (R7-proven). Accumulates both
// unnormalized branches AND row sums in one loop (linearity),
// normalizes at the end.
//   MODE 0: epilogue LN -> yh1 fp16 + x0 fp32.
//   MODE 1: epilogue out = (emb + x0 + x)/3.
// ---------------------------------------------------------------
template<int MODE>
__global__ void spmm_kernel(const __half* __restrict__ yh,
                            int rowBase,
                            const float* __restrict__ ue,
                            const float* __restrict__ ie,
                            float* __restrict__ out)
{
    int row = blockIdx.x * 8 + (threadIdx.x >> 5);
    if (row >= NN) return;
    int lane = threadIdx.x & 31;

    int ridx = rowBase + row;
    int n  = g_cnt[ridx];
    // g_rs holds block-local END (bumped by score); add part, sub n.
    int st = g_rs[ridx] + __ldg(&g_part[ridx >> 10]) - n;

    float s0 = 0.f, s1 = 0.f;
    float a0x = 0.f, a0y = 0.f, a1x = 0.f, a1y = 0.f;

    int i = 0;
    for (; i + 2 <= n; i += 2) {
        int4 cwA = __ldg(&g_csr[st + i]);
        int4 cwB = __ldg(&g_csr[st + i + 1]);
        __half2 hA = ((const __half2*)(yh + (size_t)cwA.x * D))[lane];
        __half2 hB = ((const __half2*)(yh + (size_t)cwB.x * D))[lane];
        float e0A = __int_as_float(cwA.y), e1A = __int_as_float(cwA.z);
        float e0B = __int_as_float(cwB.y), e1B = __int_as_float(cwB.z);
        float2 vA = __half22float2(hA);
        float2 vB = __half22float2(hB);
        a0x += e0A * vA.x + e0B * vB.x;
        a0y += e0A * vA.y + e0B * vB.y;
        a1x += e1A * vA.x + e1B * vB.x;
        a1y += e1A * vA.y + e1B * vB.y;
        s0 += e0A + e0B;
        s1 += e1A + e1B;
    }
    if (i < n) {
        int4 cw = __ldg(&g_csr[st + i]);
        __half2 h = ((const __half2*)(yh + (size_t)cw.x * D))[lane];
        float e0 = __int_as_float(cw.y), e1 = __int_as_float(cw.z);
        float2 v = __half22float2(h);
        a0x += e0 * v.x; a0y += e0 * v.y;
        a1x += e1 * v.x; a1y += e1 * v.y;
        s0 += e0; s1 += e1;
    }

    float i0 = 0.5f / ((s0 == 0.f) ? 1.f : s0);
    float i1 = 0.5f / ((s1 == 0.f) ? 1.f : s1);
    float ax = a0x * i0 + a1x * i1;
    float ay = a0y * i0 + a1y * i1;

    if (MODE == 0) {
        // fused LayerNorm -> yh1 (fp16), plus x0 (fp32)
        float s = ax + ay;
        #pragma unroll
        for (int o = 16; o; o >>= 1) s += __shfl_xor_sync(0xffffffffu, s, o);
        float mu = s * (1.0f / D);
        float dx = ax - mu, dy = ay - mu;
        float vs = dx * dx + dy * dy;
        #pragma unroll
        for (int o = 16; o; o >>= 1) vs += __shfl_xor_sync(0xffffffffu, vs, o);
        float inv = rsqrtf(vs * (1.0f / D) + EPS);

        ((float2*)(g_x0 + (size_t)row * D))[lane] = make_float2(ax, ay);
        ((__half2*)(g_yh1 + (size_t)row * D))[lane] =
            __floats2half2_rn(dx * inv, dy * inv);
    } else {
        const float* emb = (row < NU) ? (ue + (size_t)row * D)
                                      : (ie + (size_t)(row - NU) * D);
        float2 e = ((const float2*)emb)[lane];
        float2 x = ((const float2*)(g_x0 + (size_t)row * D))[lane];
        const float t = 1.0f / 3.0f;
        ((float2*)(out + (size_t)row * D))[lane] =
            make_float2((e.x + x.x + ax) * t, (e.y + x.y + ay) * t);
    }
}

extern "C" void kernel_launch(void* const* d_in, const int* in_sizes, int n_in,
                              void* d_out, int out_size)
{
    const float* ue   = (const float*)d_in[0];  // [NU, D]
    const float* ie   = (const float*)d_in[1];  // [NI, D]
    const float* eigs = (const float*)d_in[2];  // [NN, DE]
    const float* lam  = (const float*)d_in[3];  // [2]
    const float* pw   = (const float*)d_in[4];  // [2, NP]
    const int*   idx  = (const int*)  d_in[5];  // [2, 2, NE]
    const int*   pt   = (const int*)  d_in[6];  // [2, NE]
    float* out = (float*)d_out;

    __half* yh0 = nullptr; __half* yh1 = nullptr;
    cudaGetSymbolAddress((void**)&yh0, g_yh0);
    cudaGetSymbolAddress((void**)&yh1, g_yh1);

    int prepT = NN * DE / 2;                     // 1.2M threads (covers NN2)
    prep_kernel   <<<(prepT + 255) / 256, 256>>>(eigs);
    ln_hist_kernel<<<ROWB + HISTB, 256>>>(ue, ie, idx);
    scan_kernel   <<<NB2, SCAN_BLK>>>();

    int scoreB = (NE * 8 + 255) / 256;
    // layer 0
    score_kernel  <<<scoreB, 256>>>(yh0, idx, idx + NE, pt, lam, pw, 0);
    spmm_kernel<0><<<ROWB, 256>>>(yh0, 0, nullptr, nullptr, nullptr);
    // layer 1
    score_kernel  <<<scoreB, 256>>>(yh1, idx + 2 * NE, idx + 3 * NE,
                                    pt + NE, lam + 1, pw + NP, NN);
    spmm_kernel<1><<<ROWB, 256>>>(yh1, NN, ue, ie, out);
}

// round 11
// speedup vs baseline: 1.1505x; 1.1255x over previous
#include <cuda_runtime.h>
#include <cuda_fp16.h>

// Problem constants (fixed shapes)
#define NU 100000
#define NI 50000
#define NN 150000        // NU + NI
#define D  64
#define DE 16
#define NE 1500000
#define NP 14
#define EPS 1e-5f

#define NN2 (2 * NN)     // row counters for both layers
#define NE2 (2 * NE)     // CSR slots for both layers
#define SCAN_BLK 1024
#define NB2 ((NN2 + SCAN_BLK - 1) / SCAN_BLK)  // 293
#define ROWB ((NN + 7) / 8)                     // 18750 (8 warps/block)
#define HISTB ((NE2 / 4 + 255) / 256)           // 2930

// -------- scratch (device globals; no allocation allowed) --------
__device__ __half g_yh0[NN * D];    // LN features layer 0 (fp16)
__device__ __half g_yh1[NN * D];    // LN features layer 1 (fp16)
__device__ __half g_eh [NN * DE];   // eigs fp16
__device__ float  g_x0 [NN * D];    // layer-0 output (fp32 for final avg)
__device__ int    g_cnt[NN2];       // row degrees (both layers)
__device__ int    g_rs [NN2];       // block-local scan; bumped to local END by score
__device__ int4   g_csr[NE2];       // CSR: (col, e0 bits, e1 bits, unused)
__device__ int    g_part[512];      // per-scan-block offsets (final, exclusive)
__device__ int    g_scan_ctr;

// ---------------------------------------------------------------
// K0: zero counters, reset scan counter, eigs -> fp16.
// ---------------------------------------------------------------
__global__ void prep_kernel(const float* __restrict__ eigs)
{
    int i = blockIdx.x * blockDim.x + threadIdx.x;
    if (i == 0) g_scan_ctr = 0;
    if (i < NN2) g_cnt[i] = 0;
    if (i < NN * DE / 2) {
        float2 v = ((const float2*)eigs)[i];
        ((__half2*)g_eh)[i] = __floats2half2_rn(v.x, v.y);
    }
}

// ---------------------------------------------------------------
// K1: fused LN(layer 0) + histogram(both layers).
// g_cnt pre-zeroed in K0 (no in-kernel zeroing — R3's race).
// ---------------------------------------------------------------
__global__ void ln_hist_kernel(const float* __restrict__ ue,
                               const float* __restrict__ ie,
                               const int*   __restrict__ idx)
{
    if (blockIdx.x < ROWB) {
        int row = blockIdx.x * 8 + (threadIdx.x >> 5);
        if (row >= NN) return;
        int lane = threadIdx.x & 31;

        const float* p = (row < NU) ? (ue + (size_t)row * D)
                                    : (ie + (size_t)(row - NU) * D);
        float2 v = ((const float2*)p)[lane];

        float s = v.x + v.y;
        #pragma unroll
        for (int o = 16; o; o >>= 1) s += __shfl_xor_sync(0xffffffffu, s, o);
        float mu = s * (1.0f / D);

        float dx = v.x - mu, dy = v.y - mu;
        float vs = dx * dx + dy * dy;
        #pragma unroll
        for (int o = 16; o; o >>= 1) vs += __shfl_xor_sync(0xffffffffu, vs, o);
        float inv = rsqrtf(vs * (1.0f / D) + EPS);

        ((__half2*)(g_yh0 + (size_t)row * D))[lane] =
            __floats2half2_rn(dx * inv, dy * inv);
    } else {
        int e4 = (blockIdx.x - ROWB) * blockDim.x + threadIdx.x;
        if (e4 < NE2 / 4) {
            int layer = (e4 >= NE / 4);
            const int* rows = idx + (size_t)layer * 2 * NE;
            int4 r4 = ((const int4*)rows)[e4 - layer * (NE / 4)];
            int base = layer * NN;
            atomicAdd(&g_cnt[base + r4.x], 1);
            atomicAdd(&g_cnt[base + r4.y], 1);
            atomicAdd(&g_cnt[base + r4.z], 1);
            atomicAdd(&g_cnt[base + r4.w], 1);
        }
    }
}

// ---------------------------------------------------------------
// K2: block-local exclusive scan of g_cnt -> g_rs; last finishing
// block scans the block totals -> g_part (final offsets). Consumers
// add g_part[i >> 10] at use; no scan3 pass.
// ---------------------------------------------------------------
__device__ __forceinline__ int warp_incl_scan(int x, int lane)
{
    #pragma unroll
    for (int o = 1; o < 32; o <<= 1) {
        int t = __shfl_up_sync(0xffffffffu, x, o);
        if (lane >= o) x += t;
    }
    return x;
}

__global__ void scan_kernel()
{
    __shared__ int warpsum[32];
    __shared__ int s_total;
    __shared__ int s_isLast;

    int lane = threadIdx.x & 31;
    int wid  = threadIdx.x >> 5;
    int i = blockIdx.x * SCAN_BLK + threadIdx.x;
    int v = (i < NN2) ? g_cnt[i] : 0;

    int inc = warp_incl_scan(v, lane);
    if (lane == 31) warpsum[wid] = inc;
    __syncthreads();
    if (wid == 0) {
        int s  = warpsum[lane];
        int si = warp_incl_scan(s, lane);
        warpsum[lane] = si - s;
        if (lane == 31) s_total = si;
    }
    __syncthreads();
    int excl = inc - v + warpsum[wid];
    if (i < NN2) g_rs[i] = excl;                 // block-local exclusive scan

    if (threadIdx.x == 0) {
        g_part[blockIdx.x] = s_total;
        __threadfence();
        s_isLast = (atomicAdd(&g_scan_ctr, 1) == (int)gridDim.x - 1);
    }
    __syncthreads();

    if (s_isLast) {
        int pv = (threadIdx.x < NB2) ? g_part[threadIdx.x] : 0;
        int inc2 = warp_incl_scan(pv, lane);
        __syncthreads();
        if (lane == 31) warpsum[wid] = inc2;
        __syncthreads();
        if (wid == 0) {
            int s  = warpsum[lane];
            int si = warp_incl_scan(s, lane);
            warpsum[lane] = si - s;
        }
        __syncthreads();
        int excl2 = inc2 - pv + warpsum[wid];
        if (threadIdx.x < NB2) g_part[threadIdx.x] = excl2;
    }
}

// ---------------------------------------------------------------
// K3: scores in EDGE order, 4 lanes per TWO edges (paired) + fused
// CSR scatter. Each lane issues 8 independent 16B row loads (MLP=8).
// Index loads are coalesced int2. Epilogue: lane0 handles edge A,
// lane1 edge B (parallel exp/cursor/store).
// No row-sum atomics (sums computed in spmm via linearity).
// ---------------------------------------------------------------
__device__ __forceinline__ float dot8h(uint4 a, uint4 b)
{
    const __half2* ah = (const __half2*)&a;
    const __half2* bh = (const __half2*)&b;
    float d = 0.f;
    #pragma unroll
    for (int j = 0; j < 4; j++) {
        float2 af = __half22float2(ah[j]);
        float2 bf = __half22float2(bh[j]);
        d += af.x * bf.x + af.y * bf.y;
    }
    return d;
}

__global__ void score_kernel(const __half* __restrict__ yh,
                             const int*   __restrict__ rows,
                             const int*   __restrict__ cols,
                             const int*   __restrict__ pt,
                             const float* __restrict__ lam,
                             const float* __restrict__ pw,
                             int rowBase)
{
    int t = blockIdx.x * blockDim.x + threadIdx.x;
    int ep = t >> 2;                   // edge-pair index
    if (ep >= NE / 2) return;
    int q = t & 3;
    int eA = 2 * ep;                   // NE is even

    int2 rr = __ldg((const int2*)rows + ep);   // rows[eA], rows[eA+1]
    int2 cc = __ldg((const int2*)cols + ep);   // cols[eA], cols[eA+1]

    // 8 independent 16B loads — deep MLP
    const uint4* arA = (const uint4*)(yh + (size_t)rr.x * D);
    const uint4* acA = (const uint4*)(yh + (size_t)cc.x * D);
    const uint4* arB = (const uint4*)(yh + (size_t)rr.y * D);
    const uint4* acB = (const uint4*)(yh + (size_t)cc.y * D);
    uint4 a0 = __ldg(arA + q),     b0 = __ldg(acA + q);
    uint4 a1 = __ldg(arA + q + 4), b1 = __ldg(acA + q + 4);
    uint4 a2 = __ldg(arB + q),     b2 = __ldg(acB + q);
    uint4 a3 = __ldg(arB + q + 4), b3 = __ldg(acB + q + 4);

    // eigs fp16: lane q covers dims [4q, 4q+4)
    uint2 euA = __ldg((const uint2*)(g_eh + (size_t)rr.x * DE) + q);
    uint2 evA = __ldg((const uint2*)(g_eh + (size_t)cc.x * DE) + q);
    uint2 euB = __ldg((const uint2*)(g_eh + (size_t)rr.y * DE) + q);
    uint2 evB = __ldg((const uint2*)(g_eh + (size_t)cc.y * DE) + q);

    float dpA = dot8h(a0, b0) + dot8h(a1, b1);
    float dpB = dot8h(a2, b2) + dot8h(a3, b3);

    float2 p0, p1, q0, q1;
    p0 = __half22float2(*(__half2*)&euA.x); p1 = __half22float2(*(__half2*)&euA.y);
    q0 = __half22float2(*(__half2*)&evA.x); q1 = __half22float2(*(__half2*)&evA.y);
    float ysA = p0.x * q0.x + p0.y * q0.y + p1.x * q1.x + p1.y * q1.y;
    p0 = __half22float2(*(__half2*)&euB.x); p1 = __half22float2(*(__half2*)&euB.y);
    q0 = __half22float2(*(__half2*)&evB.x); q1 = __half22float2(*(__half2*)&evB.y);
    float ysB = p0.x * q0.x + p0.y * q0.y + p1.x * q1.x + p1.y * q1.y;

    float elam = __expf(__ldg(lam));
    float pA = dpA * 0.125f + elam * ysA;
    float pB = dpB * 0.125f + elam * ysB;
    pA += __shfl_xor_sync(0xffffffffu, pA, 1);
    pB += __shfl_xor_sync(0xffffffffu, pB, 1);
    pA += __shfl_xor_sync(0xffffffffu, pA, 2);
    pB += __shfl_xor_sync(0xffffffffu, pB, 2);

    // epilogue split across lanes: lane0 -> edge A, lane1 -> edge B
    if (q < 2) {
        int  e  = eA + q;
        int  r  = (q == 0) ? rr.x : rr.y;
        int  c  = (q == 0) ? cc.x : cc.y;
        float p = (q == 0) ? pA : pB;
        float v0 = fminf(__expf(p), 5.0f);                         // clip(exp,-5,5)
        float v1 = fminf(__expf(__ldg(pw + __ldg(pt + e))), 5.0f);
        int ridx = rowBase + r;
        int pos = atomicAdd(&g_rs[ridx], 1) + __ldg(&g_part[ridx >> 10]);
        g_csr[pos] = make_int4(c, __float_as_int(v0), __float_as_int(v1), 0);
    }
}

// ---------------------------------------------------------------
// K4: SpMM warp/row, 2-wide unroll (R7-proven). Accumulates both
// unnormalized branches AND row sums in one loop (linearity),
// normalizes at the end.
//   MODE 0: epilogue LN -> yh1 fp16 + x0 fp32.
//   MODE 1: epilogue out = (emb + x0 + x)/3.
// ---------------------------------------------------------------
template<int MODE>
__global__ void spmm_kernel(const __half* __restrict__ yh,
                            int rowBase,
                            const float* __restrict__ ue,
                            const float* __restrict__ ie,
                            float* __restrict__ out)
{
    int row = blockIdx.x * 8 + (threadIdx.x >> 5);
    if (row >= NN) return;
    int lane = threadIdx.x & 31;

    int ridx = rowBase + row;
    int n  = g_cnt[ridx];
    // g_rs holds block-local END (bumped by score); add part, sub n.
    int st = g_rs[ridx] + __ldg(&g_part[ridx >> 10]) - n;

    float s0 = 0.f, s1 = 0.f;
    float a0x = 0.f, a0y = 0.f, a1x = 0.f, a1y = 0.f;

    int i = 0;
    for (; i + 2 <= n; i += 2) {
        int4 cwA = __ldg(&g_csr[st + i]);
        int4 cwB = __ldg(&g_csr[st + i + 1]);
        __half2 hA = ((const __half2*)(yh + (size_t)cwA.x * D))[lane];
        __half2 hB = ((const __half2*)(yh + (size_t)cwB.x * D))[lane];
        float e0A = __int_as_float(cwA.y), e1A = __int_as_float(cwA.z);
        float e0B = __int_as_float(cwB.y), e1B = __int_as_float(cwB.z);
        float2 vA = __half22float2(hA);
        float2 vB = __half22float2(hB);
        a0x += e0A * vA.x + e0B * vB.x;
        a0y += e0A * vA.y + e0B * vB.y;
        a1x += e1A * vA.x + e1B * vB.x;
        a1y += e1A * vA.y + e1B * vB.y;
        s0 += e0A + e0B;
        s1 += e1A + e1B;
    }
    if (i < n) {
        int4 cw = __ldg(&g_csr[st + i]);
        __half2 h = ((const __half2*)(yh + (size_t)cw.x * D))[lane];
        float e0 = __int_as_float(cw.y), e1 = __int_as_float(cw.z);
        float2 v = __half22float2(h);
        a0x += e0 * v.x; a0y += e0 * v.y;
        a1x += e1 * v.x; a1y += e1 * v.y;
        s0 += e0; s1 += e1;
    }

    float i0 = 0.5f / ((s0 == 0.f) ? 1.f : s0);
    float i1 = 0.5f / ((s1 == 0.f) ? 1.f : s1);
    float ax = a0x * i0 + a1x * i1;
    float ay = a0y * i0 + a1y * i1;

    if (MODE == 0) {
        // fused LayerNorm -> yh1 (fp16), plus x0 (fp32)
        float s = ax + ay;
        #pragma unroll
        for (int o = 16; o; o >>= 1) s += __shfl_xor_sync(0xffffffffu, s, o);
        float mu = s * (1.0f / D);
        float dx = ax - mu, dy = ay - mu;
        float vs = dx * dx + dy * dy;
        #pragma unroll
        for (int o = 16; o; o >>= 1) vs += __shfl_xor_sync(0xffffffffu, vs, o);
        float inv = rsqrtf(vs * (1.0f / D) + EPS);

        ((float2*)(g_x0 + (size_t)row * D))[lane] = make_float2(ax, ay);
        ((__half2*)(g_yh1 + (size_t)row * D))[lane] =
            __floats2half2_rn(dx * inv, dy * inv);
    } else {
        const float* emb = (row < NU) ? (ue + (size_t)row * D)
                                      : (ie + (size_t)(row - NU) * D);
        float2 e = ((const float2*)emb)[lane];
        float2 x = ((const float2*)(g_x0 + (size_t)row * D))[lane];
        const float t = 1.0f / 3.0f;
        ((float2*)(out + (size_t)row * D))[lane] =
            make_float2((e.x + x.x + ax) * t, (e.y + x.y + ay) * t);
    }
}

extern "C" void kernel_launch(void* const* d_in, const int* in_sizes, int n_in,
                              void* d_out, int out_size)
{
    const float* ue   = (const float*)d_in[0];  // [NU, D]
    const float* ie   = (const float*)d_in[1];  // [NI, D]
    const float* eigs = (const float*)d_in[2];  // [NN, DE]
    const float* lam  = (const float*)d_in[3];  // [2]
    const float* pw   = (const float*)d_in[4];  // [2, NP]
    const int*   idx  = (const int*)  d_in[5];  // [2, 2, NE]
    const int*   pt   = (const int*)  d_in[6];  // [2, NE]
    float* out = (float*)d_out;

    __half* yh0 = nullptr; __half* yh1 = nullptr;
    cudaGetSymbolAddress((void**)&yh0, g_yh0);
    cudaGetSymbolAddress((void**)&yh1, g_yh1);

    int prepT = NN * DE / 2;                     // 1.2M threads (covers NN2)
    prep_kernel   <<<(prepT + 255) / 256, 256>>>(eigs);
    ln_hist_kernel<<<ROWB + HISTB, 256>>>(ue, ie, idx);
    scan_kernel   <<<NB2, SCAN_BLK>>>();

    int scoreB = ((NE / 2) * 4 + 255) / 256;
    // layer 0
    score_kernel  <<<scoreB, 256>>>(yh0, idx, idx + NE, pt, lam, pw, 0);
    spmm_kernel<0><<<ROWB, 256>>>(yh0, 0, nullptr, nullptr, nullptr);
    // layer 1
    score_kernel  <<<scoreB, 256>>>(yh1, idx + 2 * NE, idx + 3 * NE,
                                    pt + NE, lam + 1, pw + NP, NN);
    spmm_kernel<1><<<ROWB, 256>>>(yh1, NN, ue, ie, out);
}

// round 12
// speedup vs baseline: 1.2194x; 1.0598x over previous
#include <cuda_runtime.h>
#include <cuda_fp16.h>

// Problem constants (fixed shapes)
#define NU 100000
#define NI 50000
#define NN 150000        // NU + NI
#define D  64
#define DE 16
#define NE 1500000
#define NP 14
#define EPS 1e-5f

#define NN2 (2 * NN)     // row counters for both layers
#define NE2 (2 * NE)     // CSR slots for both layers
#define SCAN_BLK 1024
#define NB2 ((NN2 + SCAN_BLK - 1) / SCAN_BLK)  // 293
#define ROWB ((NN + 7) / 8)                     // 18750 (8 warps/block)
#define HISTB ((NE2 / 4 + 255) / 256)           // 2930

// -------- scratch (device globals; no allocation allowed) --------
__device__ __half g_yh0[NN * D];    // LN features layer 0 (fp16)
__device__ __half g_yh1[NN * D];    // LN features layer 1 (fp16)
__device__ __half g_eh [NN * DE];   // eigs fp16
__device__ float  g_x0 [NN * D];    // layer-0 output (fp32 for final avg)
__device__ int    g_cnt[NN2];       // row degrees (both layers)
__device__ int    g_rs [NN2];       // block-local scan; bumped to local END by score
__device__ int2   g_csr[NE2];       // CSR: (c | pt<<20, e0 bits) — 8 B/slot
__device__ float  g_pwx[2 * NP];    // clip(exp(path_w),5) per layer
__device__ int    g_part[512];      // per-scan-block offsets (final, exclusive)
__device__ int    g_scan_ctr;

// ---------------------------------------------------------------
// K0: zero counters, reset scan counter, eigs -> fp16, pwx table.
// ---------------------------------------------------------------
__global__ void prep_kernel(const float* __restrict__ eigs,
                            const float* __restrict__ pw)
{
    int i = blockIdx.x * blockDim.x + threadIdx.x;
    if (i == 0) g_scan_ctr = 0;
    if (i < 2 * NP) g_pwx[i] = fminf(__expf(__ldg(pw + i)), 5.0f);
    if (i < NN2) g_cnt[i] = 0;
    if (i < NN * DE / 2) {
        float2 v = ((const float2*)eigs)[i];
        ((__half2*)g_eh)[i] = __floats2half2_rn(v.x, v.y);
    }
}

// ---------------------------------------------------------------
// K1: fused LN(layer 0) + histogram(both layers).
// g_cnt pre-zeroed in K0 (no in-kernel zeroing — R3's race).
// ---------------------------------------------------------------
__global__ void ln_hist_kernel(const float* __restrict__ ue,
                               const float* __restrict__ ie,
                               const int*   __restrict__ idx)
{
    if (blockIdx.x < ROWB) {
        int row = blockIdx.x * 8 + (threadIdx.x >> 5);
        if (row >= NN) return;
        int lane = threadIdx.x & 31;

        const float* p = (row < NU) ? (ue + (size_t)row * D)
                                    : (ie + (size_t)(row - NU) * D);
        float2 v = ((const float2*)p)[lane];

        float s = v.x + v.y;
        #pragma unroll
        for (int o = 16; o; o >>= 1) s += __shfl_xor_sync(0xffffffffu, s, o);
        float mu = s * (1.0f / D);

        float dx = v.x - mu, dy = v.y - mu;
        float vs = dx * dx + dy * dy;
        #pragma unroll
        for (int o = 16; o; o >>= 1) vs += __shfl_xor_sync(0xffffffffu, vs, o);
        float inv = rsqrtf(vs * (1.0f / D) + EPS);

        ((__half2*)(g_yh0 + (size_t)row * D))[lane] =
            __floats2half2_rn(dx * inv, dy * inv);
    } else {
        int e4 = (blockIdx.x - ROWB) * blockDim.x + threadIdx.x;
        if (e4 < NE2 / 4) {
            int layer = (e4 >= NE / 4);
            const int* rows = idx + (size_t)layer * 2 * NE;
            int4 r4 = ((const int4*)rows)[e4 - layer * (NE / 4)];
            int base = layer * NN;
            atomicAdd(&g_cnt[base + r4.x], 1);
            atomicAdd(&g_cnt[base + r4.y], 1);
            atomicAdd(&g_cnt[base + r4.z], 1);
            atomicAdd(&g_cnt[base + r4.w], 1);
        }
    }
}

// ---------------------------------------------------------------
// K2: block-local exclusive scan of g_cnt -> g_rs; last finishing
// block scans the block totals -> g_part (final offsets).
// ---------------------------------------------------------------
__device__ __forceinline__ int warp_incl_scan(int x, int lane)
{
    #pragma unroll
    for (int o = 1; o < 32; o <<= 1) {
        int t = __shfl_up_sync(0xffffffffu, x, o);
        if (lane >= o) x += t;
    }
    return x;
}

__global__ void scan_kernel()
{
    __shared__ int warpsum[32];
    __shared__ int s_total;
    __shared__ int s_isLast;

    int lane = threadIdx.x & 31;
    int wid  = threadIdx.x >> 5;
    int i = blockIdx.x * SCAN_BLK + threadIdx.x;
    int v = (i < NN2) ? g_cnt[i] : 0;

    int inc = warp_incl_scan(v, lane);
    if (lane == 31) warpsum[wid] = inc;
    __syncthreads();
    if (wid == 0) {
        int s  = warpsum[lane];
        int si = warp_incl_scan(s, lane);
        warpsum[lane] = si - s;
        if (lane == 31) s_total = si;
    }
    __syncthreads();
    int excl = inc - v + warpsum[wid];
    if (i < NN2) g_rs[i] = excl;                 // block-local exclusive scan

    if (threadIdx.x == 0) {
        g_part[blockIdx.x] = s_total;
        __threadfence();
        s_isLast = (atomicAdd(&g_scan_ctr, 1) == (int)gridDim.x - 1);
    }
    __syncthreads();

    if (s_isLast) {
        int pv = (threadIdx.x < NB2) ? g_part[threadIdx.x] : 0;
        int inc2 = warp_incl_scan(pv, lane);
        __syncthreads();
        if (lane == 31) warpsum[wid] = inc2;
        __syncthreads();
        if (wid == 0) {
            int s  = warpsum[lane];
            int si = warp_incl_scan(s, lane);
            warpsum[lane] = si - s;
        }
        __syncthreads();
        int excl2 = inc2 - pv + warpsum[wid];
        if (threadIdx.x < NB2) g_part[threadIdx.x] = excl2;
    }
}

// ---------------------------------------------------------------
// K3: scores in EDGE order, 4 lanes per TWO edges (paired) + fused
// CSR scatter (int2: c|pt<<20, e0). No exp(pw) here — spmm looks it
// up via the precomputed table.
// ---------------------------------------------------------------
__device__ __forceinline__ float dot8h(uint4 a, uint4 b)
{
    const __half2* ah = (const __half2*)&a;
    const __half2* bh = (const __half2*)&b;
    float d = 0.f;
    #pragma unroll
    for (int j = 0; j < 4; j++) {
        float2 af = __half22float2(ah[j]);
        float2 bf = __half22float2(bh[j]);
        d += af.x * bf.x + af.y * bf.y;
    }
    return d;
}

__global__ void score_kernel(const __half* __restrict__ yh,
                             const int*   __restrict__ rows,
                             const int*   __restrict__ cols,
                             const int*   __restrict__ pt,
                             const float* __restrict__ lam,
                             int rowBase)
{
    int t = blockIdx.x * blockDim.x + threadIdx.x;
    int ep = t >> 2;                   // edge-pair index
    if (ep >= NE / 2) return;
    int q = t & 3;

    int2 rr = __ldg((const int2*)rows + ep);   // rows[2ep], rows[2ep+1]
    int2 cc = __ldg((const int2*)cols + ep);

    // 8 independent 16B loads — deep MLP
    const uint4* arA = (const uint4*)(yh + (size_t)rr.x * D);
    const uint4* acA = (const uint4*)(yh + (size_t)cc.x * D);
    const uint4* arB = (const uint4*)(yh + (size_t)rr.y * D);
    const uint4* acB = (const uint4*)(yh + (size_t)cc.y * D);
    uint4 a0 = __ldg(arA + q),     b0 = __ldg(acA + q);
    uint4 a1 = __ldg(arA + q + 4), b1 = __ldg(acA + q + 4);
    uint4 a2 = __ldg(arB + q),     b2 = __ldg(acB + q);
    uint4 a3 = __ldg(arB + q + 4), b3 = __ldg(acB + q + 4);

    // eigs fp16: lane q covers dims [4q, 4q+4)
    uint2 euA = __ldg((const uint2*)(g_eh + (size_t)rr.x * DE) + q);
    uint2 evA = __ldg((const uint2*)(g_eh + (size_t)cc.x * DE) + q);
    uint2 euB = __ldg((const uint2*)(g_eh + (size_t)rr.y * DE) + q);
    uint2 evB = __ldg((const uint2*)(g_eh + (size_t)cc.y * DE) + q);

    float dpA = dot8h(a0, b0) + dot8h(a1, b1);
    float dpB = dot8h(a2, b2) + dot8h(a3, b3);

    float2 p0, p1, q0, q1;
    p0 = __half22float2(*(__half2*)&euA.x); p1 = __half22float2(*(__half2*)&euA.y);
    q0 = __half22float2(*(__half2*)&evA.x); q1 = __half22float2(*(__half2*)&evA.y);
    float ysA = p0.x * q0.x + p0.y * q0.y + p1.x * q1.x + p1.y * q1.y;
    p0 = __half22float2(*(__half2*)&euB.x); p1 = __half22float2(*(__half2*)&euB.y);
    q0 = __half22float2(*(__half2*)&evB.x); q1 = __half22float2(*(__half2*)&evB.y);
    float ysB = p0.x * q0.x + p0.y * q0.y + p1.x * q1.x + p1.y * q1.y;

    float elam = __expf(__ldg(lam));
    float pA = dpA * 0.125f + elam * ysA;
    float pB = dpB * 0.125f + elam * ysB;
    pA += __shfl_xor_sync(0xffffffffu, pA, 1);
    pB += __shfl_xor_sync(0xffffffffu, pB, 1);
    pA += __shfl_xor_sync(0xffffffffu, pA, 2);
    pB += __shfl_xor_sync(0xffffffffu, pB, 2);

    // epilogue split across lanes: lane0 -> edge A, lane1 -> edge B
    if (q < 2) {
        int2 pp = __ldg((const int2*)pt + ep);     // pt[2ep], pt[2ep+1]
        int  r   = (q == 0) ? rr.x : rr.y;
        int  c   = (q == 0) ? cc.x : cc.y;
        int  ptv = (q == 0) ? pp.x : pp.y;
        float p  = (q == 0) ? pA : pB;
        float v0 = fminf(__expf(p), 5.0f);                     // clip(exp,-5,5)
        int ridx = rowBase + r;
        int pos = atomicAdd(&g_rs[ridx], 1) + __ldg(&g_part[ridx >> 10]);
        g_csr[pos] = make_int2(c | (ptv << 20), __float_as_int(v0));
    }
}

// ---------------------------------------------------------------
// K4: SpMM warp/row. CSR slots are 8B; main loop loads TWO slots per
// int4 (16B) instruction (peel one if row start is odd). e1 comes
// from the 14-entry pwx table (L1-resident broadcast).
//   MODE 0: epilogue LN -> yh1 fp16 + x0 fp32.
//   MODE 1: epilogue out = (emb + x0 + x)/3.
// ---------------------------------------------------------------
template<int MODE>
__global__ void spmm_kernel(const __half* __restrict__ yh,
                            int rowBase,
                            const float* __restrict__ pwx,   // &g_pwx[l*NP]
                            const float* __restrict__ ue,
                            const float* __restrict__ ie,
                            float* __restrict__ out)
{
    int row = blockIdx.x * 8 + (threadIdx.x >> 5);
    if (row >= NN) return;
    int lane = threadIdx.x & 31;

    int ridx = rowBase + row;
    int n  = g_cnt[ridx];
    // g_rs holds block-local END (bumped by score); add part, sub n.
    int st  = g_rs[ridx] + __ldg(&g_part[ridx >> 10]) - n;
    int end = st + n;

    float s0 = 0.f, s1 = 0.f;
    float a0x = 0.f, a0y = 0.f, a1x = 0.f, a1y = 0.f;

    int i = st;
    if ((i & 1) && i < end) {                    // peel to even index
        int2 cw = __ldg(&g_csr[i]);
        int   c   = cw.x & 0xFFFFF;
        float e1  = __ldg(pwx + (cw.x >> 20));
        float e0  = __int_as_float(cw.y);
        float2 v  = __half22float2(((const __half2*)(yh + (size_t)c * D))[lane]);
        a0x += e0 * v.x; a0y += e0 * v.y;
        a1x += e1 * v.x; a1y += e1 * v.y;
        s0 += e0; s1 += e1;
        i++;
    }
    for (; i + 2 <= end; i += 2) {
        int4 two = __ldg((const int4*)g_csr + (i >> 1));   // slots i, i+1
        int   cA  = two.x & 0xFFFFF;
        int   cB  = two.z & 0xFFFFF;
        float e1A = __ldg(pwx + (two.x >> 20));
        float e1B = __ldg(pwx + (two.z >> 20));
        float e0A = __int_as_float(two.y);
        float e0B = __int_as_float(two.w);
        __half2 hA = ((const __half2*)(yh + (size_t)cA * D))[lane];
        __half2 hB = ((const __half2*)(yh + (size_t)cB * D))[lane];
        float2 vA = __half22float2(hA);
        float2 vB = __half22float2(hB);
        a0x += e0A * vA.x + e0B * vB.x;
        a0y += e0A * vA.y + e0B * vB.y;
        a1x += e1A * vA.x + e1B * vB.x;
        a1y += e1A * vA.y + e1B * vB.y;
        s0 += e0A + e0B;
        s1 += e1A + e1B;
    }
    if (i < end) {
        int2 cw = __ldg(&g_csr[i]);
        int   c   = cw.x & 0xFFFFF;
        float e1  = __ldg(pwx + (cw.x >> 20));
        float e0  = __int_as_float(cw.y);
        float2 v  = __half22float2(((const __half2*)(yh + (size_t)c * D))[lane]);
        a0x += e0 * v.x; a0y += e0 * v.y;
        a1x += e1 * v.x; a1y += e1 * v.y;
        s0 += e0; s1 += e1;
    }

    float i0 = 0.5f / ((s0 == 0.f) ? 1.f : s0);
    float i1 = 0.5f / ((s1 == 0.f) ? 1.f : s1);
    float ax = a0x * i0 + a1x * i1;
    float ay = a0y * i0 + a1y * i1;

    if (MODE == 0) {
        // fused LayerNorm -> yh1 (fp16), plus x0 (fp32)
        float s = ax + ay;
        #pragma unroll
        for (int o = 16; o; o >>= 1) s += __shfl_xor_sync(0xffffffffu, s, o);
        float mu = s * (1.0f / D);
        float dx = ax - mu, dy = ay - mu;
        float vs = dx * dx + dy * dy;
        #pragma unroll
        for (int o = 16; o; o >>= 1) vs += __shfl_xor_sync(0xffffffffu, vs, o);
        float inv = rsqrtf(vs * (1.0f / D) + EPS);

        ((float2*)(g_x0 + (size_t)row * D))[lane] = make_float2(ax, ay);
        ((__half2*)(g_yh1 + (size_t)row * D))[lane] =
            __floats2half2_rn(dx * inv, dy * inv);
    } else {
        const float* emb = (row < NU) ? (ue + (size_t)row * D)
                                      : (ie + (size_t)(row - NU) * D);
        float2 e = ((const float2*)emb)[lane];
        float2 x = ((const float2*)(g_x0 + (size_t)row * D))[lane];
        const float t = 1.0f / 3.0f;
        ((float2*)(out + (size_t)row * D))[lane] =
            make_float2((e.x + x.x + ax) * t, (e.y + x.y + ay) * t);
    }
}

extern "C" void kernel_launch(void* const* d_in, const int* in_sizes, int n_in,
                              void* d_out, int out_size)
{
    const float* ue   = (const float*)d_in[0];  // [NU, D]
    const float* ie   = (const float*)d_in[1];  // [NI, D]
    const float* eigs = (const float*)d_in[2];  // [NN, DE]
    const float* lam  = (const float*)d_in[3];  // [2]
    const float* pw   = (const float*)d_in[4];  // [2, NP]
    const int*   idx  = (const int*)  d_in[5];  // [2, 2, NE]
    const int*   pt   = (const int*)  d_in[6];  // [2, NE]
    float* out = (float*)d_out;

    __half* yh0 = nullptr; __half* yh1 = nullptr; float* pwx = nullptr;
    cudaGetSymbolAddress((void**)&yh0, g_yh0);
    cudaGetSymbolAddress((void**)&yh1, g_yh1);
    cudaGetSymbolAddress((void**)&pwx, g_pwx);

    int prepT = NN * DE / 2;                     // 1.2M threads (covers NN2)
    prep_kernel   <<<(prepT + 255) / 256, 256>>>(eigs, pw);
    ln_hist_kernel<<<ROWB + HISTB, 256>>>(ue, ie, idx);
    scan_kernel   <<<NB2, SCAN_BLK>>>();

    int scoreB = ((NE / 2) * 4 + 255) / 256;
    // layer 0
    score_kernel  <<<scoreB, 256>>>(yh0, idx, idx + NE, pt, lam, 0);
    spmm_kernel<0><<<ROWB, 256>>>(yh0, 0, pwx, nullptr, nullptr, nullptr);
    // layer 1
    score_kernel  <<<scoreB, 256>>>(yh1, idx + 2 * NE, idx + 3 * NE,
                                    pt + NE, lam + 1, NN);
    spmm_kernel<1><<<ROWB, 256>>>(yh1, NN, pwx + NP, ue, ie, out);
}

// round 13
// speedup vs baseline: 1.2563x; 1.0303x over previous
#include <cuda_runtime.h>
#include <cuda_fp16.h>

// Problem constants (fixed shapes)
#define NU 100000
#define NI 50000
#define NN 150000        // NU + NI
#define D  64
#define DE 16
#define NE 1500000
#define NP 14
#define EPS 1e-5f

#define NN2 (2 * NN)     // row counters for both layers
#define NE2 (2 * NE)     // CSR slots for both layers
#define SCAN_BLK 1024
#define NB2 ((NN2 + SCAN_BLK - 1) / SCAN_BLK)  // 293
#define ROWB ((NN + 7) / 8)                     // 18750 (8 warps/block)
#define HISTB ((NE2 / 4 + 255) / 256)           // 2930

// -------- scratch (device globals; no allocation allowed) --------
__device__ __half g_yh0[NN * D];    // LN features layer 0 (fp16)
__device__ __half g_yh1[NN * D];    // LN features layer 1 (fp16)
__device__ __half g_eh [NN * DE];   // eigs fp16
__device__ float  g_x0 [NN * D];    // layer-0 output (fp32 for final avg)
__device__ int    g_cnt[NN2];       // row degrees (both layers)
__device__ int    g_rs [NN2];       // block-local scan; bumped to local END by score
__device__ int2   g_csr[NE2];       // CSR: (c | pt<<20, e0 bits) — 8 B/slot
__device__ float  g_pwx[2 * NP];    // clip(exp(path_w),5) per layer
__device__ int    g_part[512];      // per-scan-block offsets (final, exclusive)
__device__ int    g_scan_ctr;

// ---------------------------------------------------------------
// K0: zero counters, reset scan counter, eigs -> fp16, pwx table.
// ---------------------------------------------------------------
__global__ void prep_kernel(const float* __restrict__ eigs,
                            const float* __restrict__ pw)
{
    int i = blockIdx.x * blockDim.x + threadIdx.x;
    if (i == 0) g_scan_ctr = 0;
    if (i < 2 * NP) g_pwx[i] = fminf(__expf(__ldg(pw + i)), 5.0f);
    if (i < NN2) g_cnt[i] = 0;
    if (i < NN * DE / 2) {
        float2 v = ((const float2*)eigs)[i];
        ((__half2*)g_eh)[i] = __floats2half2_rn(v.x, v.y);
    }
}

// ---------------------------------------------------------------
// K1: fused LN(layer 0) + histogram(both layers).
// g_cnt pre-zeroed in K0 (no in-kernel zeroing — R3's race).
// ---------------------------------------------------------------
__global__ void ln_hist_kernel(const float* __restrict__ ue,
                               const float* __restrict__ ie,
                               const int*   __restrict__ idx)
{
    if (blockIdx.x < ROWB) {
        int row = blockIdx.x * 8 + (threadIdx.x >> 5);
        if (row >= NN) return;
        int lane = threadIdx.x & 31;

        const float* p = (row < NU) ? (ue + (size_t)row * D)
                                    : (ie + (size_t)(row - NU) * D);
        float2 v = ((const float2*)p)[lane];

        float s = v.x + v.y;
        #pragma unroll
        for (int o = 16; o; o >>= 1) s += __shfl_xor_sync(0xffffffffu, s, o);
        float mu = s * (1.0f / D);

        float dx = v.x - mu, dy = v.y - mu;
        float vs = dx * dx + dy * dy;
        #pragma unroll
        for (int o = 16; o; o >>= 1) vs += __shfl_xor_sync(0xffffffffu, vs, o);
        float inv = rsqrtf(vs * (1.0f / D) + EPS);

        ((__half2*)(g_yh0 + (size_t)row * D))[lane] =
            __floats2half2_rn(dx * inv, dy * inv);
    } else {
        int e4 = (blockIdx.x - ROWB) * blockDim.x + threadIdx.x;
        if (e4 < NE2 / 4) {
            int layer = (e4 >= NE / 4);
            const int* rows = idx + (size_t)layer * 2 * NE;
            int4 r4 = ((const int4*)rows)[e4 - layer * (NE / 4)];
            int base = layer * NN;
            atomicAdd(&g_cnt[base + r4.x], 1);
            atomicAdd(&g_cnt[base + r4.y], 1);
            atomicAdd(&g_cnt[base + r4.z], 1);
            atomicAdd(&g_cnt[base + r4.w], 1);
        }
    }
}

// ---------------------------------------------------------------
// K2: block-local exclusive scan of g_cnt -> g_rs; last finishing
// block scans the block totals -> g_part (final offsets).
// ---------------------------------------------------------------
__device__ __forceinline__ int warp_incl_scan(int x, int lane)
{
    #pragma unroll
    for (int o = 1; o < 32; o <<= 1) {
        int t = __shfl_up_sync(0xffffffffu, x, o);
        if (lane >= o) x += t;
    }
    return x;
}

__global__ void scan_kernel()
{
    __shared__ int warpsum[32];
    __shared__ int s_total;
    __shared__ int s_isLast;

    int lane = threadIdx.x & 31;
    int wid  = threadIdx.x >> 5;
    int i = blockIdx.x * SCAN_BLK + threadIdx.x;
    int v = (i < NN2) ? g_cnt[i] : 0;

    int inc = warp_incl_scan(v, lane);
    if (lane == 31) warpsum[wid] = inc;
    __syncthreads();
    if (wid == 0) {
        int s  = warpsum[lane];
        int si = warp_incl_scan(s, lane);
        warpsum[lane] = si - s;
        if (lane == 31) s_total = si;
    }
    __syncthreads();
    int excl = inc - v + warpsum[wid];
    if (i < NN2) g_rs[i] = excl;                 // block-local exclusive scan

    if (threadIdx.x == 0) {
        g_part[blockIdx.x] = s_total;
        __threadfence();
        s_isLast = (atomicAdd(&g_scan_ctr, 1) == (int)gridDim.x - 1);
    }
    __syncthreads();

    if (s_isLast) {
        int pv = (threadIdx.x < NB2) ? g_part[threadIdx.x] : 0;
        int inc2 = warp_incl_scan(pv, lane);
        __syncthreads();
        if (lane == 31) warpsum[wid] = inc2;
        __syncthreads();
        if (wid == 0) {
            int s  = warpsum[lane];
            int si = warp_incl_scan(s, lane);
            warpsum[lane] = si - s;
        }
        __syncthreads();
        int excl2 = inc2 - pv + warpsum[wid];
        if (threadIdx.x < NB2) g_part[threadIdx.x] = excl2;
    }
}

// ---------------------------------------------------------------
// K3: scores in EDGE order, 4 lanes per TWO edges (paired) + fused
// CSR scatter (int2: c|pt<<20, e0). Feature dot uses HFMA2 into a
// half2 accumulator (8 HFMA2/edge/lane instead of ~48 cvt+FFMA);
// eigs dot stays fp32 (error budget). Sums computed in spmm.
// ---------------------------------------------------------------
__device__ __forceinline__ __half2 fma8h(uint4 a, uint4 b, __half2 acc)
{
    const __half2* ah = (const __half2*)&a;
    const __half2* bh = (const __half2*)&b;
    acc = __hfma2(ah[0], bh[0], acc);
    acc = __hfma2(ah[1], bh[1], acc);
    acc = __hfma2(ah[2], bh[2], acc);
    acc = __hfma2(ah[3], bh[3], acc);
    return acc;
}

__global__ void score_kernel(const __half* __restrict__ yh,
                             const int*   __restrict__ rows,
                             const int*   __restrict__ cols,
                             const int*   __restrict__ pt,
                             const float* __restrict__ lam,
                             int rowBase)
{
    int t = blockIdx.x * blockDim.x + threadIdx.x;
    int ep = t >> 2;                   // edge-pair index
    if (ep >= NE / 2) return;
    int q = t & 3;

    int2 rr = __ldg((const int2*)rows + ep);   // rows[2ep], rows[2ep+1]
    int2 cc = __ldg((const int2*)cols + ep);

    // 8 independent 16B loads — deep MLP
    const uint4* arA = (const uint4*)(yh + (size_t)rr.x * D);
    const uint4* acA = (const uint4*)(yh + (size_t)cc.x * D);
    const uint4* arB = (const uint4*)(yh + (size_t)rr.y * D);
    const uint4* acB = (const uint4*)(yh + (size_t)cc.y * D);
    uint4 a0 = __ldg(arA + q),     b0 = __ldg(acA + q);
    uint4 a1 = __ldg(arA + q + 4), b1 = __ldg(acA + q + 4);
    uint4 a2 = __ldg(arB + q),     b2 = __ldg(acB + q);
    uint4 a3 = __ldg(arB + q + 4), b3 = __ldg(acB + q + 4);

    // eigs fp16: lane q covers dims [4q, 4q+4)
    uint2 euA = __ldg((const uint2*)(g_eh + (size_t)rr.x * DE) + q);
    uint2 evA = __ldg((const uint2*)(g_eh + (size_t)cc.x * DE) + q);
    uint2 euB = __ldg((const uint2*)(g_eh + (size_t)rr.y * DE) + q);
    uint2 evB = __ldg((const uint2*)(g_eh + (size_t)cc.y * DE) + q);

    // feature dots in half2 (8 HFMA2 per edge)
    __half2 hz = __floats2half2_rn(0.f, 0.f);
    __half2 accA = fma8h(a1, b1, fma8h(a0, b0, hz));
    __half2 accB = fma8h(a3, b3, fma8h(a2, b2, hz));
    float2 fA = __half22float2(accA);
    float2 fB = __half22float2(accB);
    float dpA = fA.x + fA.y;
    float dpB = fB.x + fB.y;

    // eigs dots in fp32
    float2 p0, p1, q0, q1;
    p0 = __half22float2(*(__half2*)&euA.x); p1 = __half22float2(*(__half2*)&euA.y);
    q0 = __half22float2(*(__half2*)&evA.x); q1 = __half22float2(*(__half2*)&evA.y);
    float ysA = p0.x * q0.x + p0.y * q0.y + p1.x * q1.x + p1.y * q1.y;
    p0 = __half22float2(*(__half2*)&euB.x); p1 = __half22float2(*(__half2*)&euB.y);
    q0 = __half22float2(*(__half2*)&evB.x); q1 = __half22float2(*(__half2*)&evB.y);
    float ysB = p0.x * q0.x + p0.y * q0.y + p1.x * q1.x + p1.y * q1.y;

    float elam = __expf(__ldg(lam));
    float pA = dpA * 0.125f + elam * ysA;
    float pB = dpB * 0.125f + elam * ysB;
    pA += __shfl_xor_sync(0xffffffffu, pA, 1);
    pB += __shfl_xor_sync(0xffffffffu, pB, 1);
    pA += __shfl_xor_sync(0xffffffffu, pA, 2);
    pB += __shfl_xor_sync(0xffffffffu, pB, 2);

    // epilogue split across lanes: lane0 -> edge A, lane1 -> edge B
    if (q < 2) {
        int2 pp = __ldg((const int2*)pt + ep);     // pt[2ep], pt[2ep+1]
        int  r   = (q == 0) ? rr.x : rr.y;
        int  c   = (q == 0) ? cc.x : cc.y;
        int  ptv = (q == 0) ? pp.x : pp.y;
        float p  = (q == 0) ? pA : pB;
        float v0 = fminf(__expf(p), 5.0f);                     // clip(exp,-5,5)
        int ridx = rowBase + r;
        int pos = atomicAdd(&g_rs[ridx], 1) + __ldg(&g_part[ridx >> 10]);
        g_csr[pos] = make_int2(c | (ptv << 20), __float_as_int(v0));
    }
}

// ---------------------------------------------------------------
// K4: SpMM warp/row. CSR slots are 8B; main loop loads TWO slots per
// int4 (16B) instruction (peel one if row start is odd). e1 comes
// from the 14-entry pwx table (L1-resident broadcast). fp32 math.
//   MODE 0: epilogue LN -> yh1 fp16 + x0 fp32.
//   MODE 1: epilogue out = (emb + x0 + x)/3.
// ---------------------------------------------------------------
template<int MODE>
__global__ void spmm_kernel(const __half* __restrict__ yh,
                            int rowBase,
                            const float* __restrict__ pwx,   // &g_pwx[l*NP]
                            const float* __restrict__ ue,
                            const float* __restrict__ ie,
                            float* __restrict__ out)
{
    int row = blockIdx.x * 8 + (threadIdx.x >> 5);
    if (row >= NN) return;
    int lane = threadIdx.x & 31;

    int ridx = rowBase + row;
    int n  = g_cnt[ridx];
    // g_rs holds block-local END (bumped by score); add part, sub n.
    int st  = g_rs[ridx] + __ldg(&g_part[ridx >> 10]) - n;
    int end = st + n;

    float s0 = 0.f, s1 = 0.f;
    float a0x = 0.f, a0y = 0.f, a1x = 0.f, a1y = 0.f;

    int i = st;
    if ((i & 1) && i < end) {                    // peel to even index
        int2 cw = __ldg(&g_csr[i]);
        int   c   = cw.x & 0xFFFFF;
        float e1  = __ldg(pwx + (cw.x >> 20));
        float e0  = __int_as_float(cw.y);
        float2 v  = __half22float2(((const __half2*)(yh + (size_t)c * D))[lane]);
        a0x += e0 * v.x; a0y += e0 * v.y;
        a1x += e1 * v.x; a1y += e1 * v.y;
        s0 += e0; s1 += e1;
        i++;
    }
    for (; i + 2 <= end; i += 2) {
        int4 two = __ldg((const int4*)g_csr + (i >> 1));   // slots i, i+1
        int   cA  = two.x & 0xFFFFF;
        int   cB  = two.z & 0xFFFFF;
        float e1A = __ldg(pwx + (two.x >> 20));
        float e1B = __ldg(pwx + (two.z >> 20));
        float e0A = __int_as_float(two.y);
        float e0B = __int_as_float(two.w);
        __half2 hA = ((const __half2*)(yh + (size_t)cA * D))[lane];
        __half2 hB = ((const __half2*)(yh + (size_t)cB * D))[lane];
        float2 vA = __half22float2(hA);
        float2 vB = __half22float2(hB);
        a0x += e0A * vA.x + e0B * vB.x;
        a0y += e0A * vA.y + e0B * vB.y;
        a1x += e1A * vA.x + e1B * vB.x;
        a1y += e1A * vA.y + e1B * vB.y;
        s0 += e0A + e0B;
        s1 += e1A + e1B;
    }
    if (i < end) {
        int2 cw = __ldg(&g_csr[i]);
        int   c   = cw.x & 0xFFFFF;
        float e1  = __ldg(pwx + (cw.x >> 20));
        float e0  = __int_as_float(cw.y);
        float2 v  = __half22float2(((const __half2*)(yh + (size_t)c * D))[lane]);
        a0x += e0 * v.x; a0y += e0 * v.y;
        a1x += e1 * v.x; a1y += e1 * v.y;
        s0 += e0; s1 += e1;
    }

    float i0 = 0.5f / ((s0 == 0.f) ? 1.f : s0);
    float i1 = 0.5f / ((s1 == 0.f) ? 1.f : s1);
    float ax = a0x * i0 + a1x * i1;
    float ay = a0y * i0 + a1y * i1;

    if (MODE == 0) {
        // fused LayerNorm -> yh1 (fp16), plus x0 (fp32)
        float s = ax + ay;
        #pragma unroll
        for (int o = 16; o; o >>= 1) s += __shfl_xor_sync(0xffffffffu, s, o);
        float mu = s * (1.0f / D);
        float dx = ax - mu, dy = ay - mu;
        float vs = dx * dx + dy * dy;
        #pragma unroll
        for (int o = 16; o; o >>= 1) vs += __shfl_xor_sync(0xffffffffu, vs, o);
        float inv = rsqrtf(vs * (1.0f / D) + EPS);

        ((float2*)(g_x0 + (size_t)row * D))[lane] = make_float2(ax, ay);
        ((__half2*)(g_yh1 + (size_t)row * D))[lane] =
            __floats2half2_rn(dx * inv, dy * inv);
    } else {
        const float* emb = (row < NU) ? (ue + (size_t)row * D)
                                      : (ie + (size_t)(row - NU) * D);
        float2 e = ((const float2*)emb)[lane];
        float2 x = ((const float2*)(g_x0 + (size_t)row * D))[lane];
        const float t = 1.0f / 3.0f;
        ((float2*)(out + (size_t)row * D))[lane] =
            make_float2((e.x + x.x + ax) * t, (e.y + x.y + ay) * t);
    }
}

extern "C" void kernel_launch(void* const* d_in, const int* in_sizes, int n_in,
                              void* d_out, int out_size)
{
    const float* ue   = (const float*)d_in[0];  // [NU, D]
    const float* ie   = (const float*)d_in[1];  // [NI, D]
    const float* eigs = (const float*)d_in[2];  // [NN, DE]
    const float* lam  = (const float*)d_in[3];  // [2]
    const float* pw   = (const float*)d_in[4];  // [2, NP]
    const int*   idx  = (const int*)  d_in[5];  // [2, 2, NE]
    const int*   pt   = (const int*)  d_in[6];  // [2, NE]
    float* out = (float*)d_out;

    __half* yh0 = nullptr; __half* yh1 = nullptr; float* pwx = nullptr;
    cudaGetSymbolAddress((void**)&yh0, g_yh0);
    cudaGetSymbolAddress((void**)&yh1, g_yh1);
    cudaGetSymbolAddress((void**)&pwx, g_pwx);

    int prepT = NN * DE / 2;                     // 1.2M threads (covers NN2)
    prep_kernel   <<<(prepT + 255) / 256, 256>>>(eigs, pw);
    ln_hist_kernel<<<ROWB + HISTB, 256>>>(ue, ie, idx);
    scan_kernel   <<<NB2, SCAN_BLK>>>();

    int scoreB = ((NE / 2) * 4 + 255) / 256;
    // layer 0
    score_kernel  <<<scoreB, 256>>>(yh0, idx, idx + NE, pt, lam, 0);
    spmm_kernel<0><<<ROWB, 256>>>(yh0, 0, pwx, nullptr, nullptr, nullptr);
    // layer 1
    score_kernel  <<<scoreB, 256>>>(yh1, idx + 2 * NE, idx + 3 * NE,
                                    pt + NE, lam + 1, NN);
    spmm_kernel<1><<<ROWB, 256>>>(yh1, NN, pwx + NP, ue, ie, out);
}